// round 4
// baseline (speedup 1.0000x reference)
#include <cuda_runtime.h>
#include <math.h>

#define N_NODES 50000
#define N_EDGES 600000
#define N_RELS  500
#define DIM     128
#define SCAN_CHUNKS ((N_NODES + 1023) / 1024)   // 49

// ---- scratch (no allocations allowed) ----
__device__ __align__(16) float g_m_node[N_NODES * DIM];
__device__ __align__(16) float g_m_rel[N_RELS * DIM];
__device__ float g_s_src[N_NODES];
__device__ float g_s_tgt[N_NODES];
__device__ float g_s_rel[N_RELS];
__device__ float g_dummy[N_RELS];
__device__ int   g_count[N_NODES];       // zero-init; re-zeroed by k_scan_add each run
__device__ int   g_offset[N_NODES + 1];
__device__ int   g_cursor[N_NODES];
__device__ int   g_blocksum[SCAN_CHUNKS];
__device__ int   g_carry[SCAN_CHUNKS];
__device__ unsigned g_epack[N_EDGES];    // src | rel<<16  (src<65536, rel<500)

// ---------------------------------------------------------------------------
__device__ __forceinline__ unsigned long long fma2(unsigned long long a,
                                                   unsigned long long b,
                                                   unsigned long long c) {
    unsigned long long d;
    asm("fma.rn.f32x2 %0, %1, %2, %3;" : "=l"(d) : "l"(a), "l"(b), "l"(c));
    return d;
}
__device__ __forceinline__ unsigned long long pack2(float x) {
    unsigned long long d;
    asm("mov.b64 %0, {%1, %1};" : "=l"(d) : "r"(__float_as_uint(x)));
    return d;
}
union F4U { float4 f4; unsigned long long u[2]; };

// ---------------------------------------------------------------------------
// Row transform: m = x @ W^T + b ; s1 = x.v1 ; s2 = x.v2
// One block = 64 rows (8 warps x 8 rows). W^T staged in smem, f32x2 FFMA,
// x broadcast loads vectorized as float4 per 4 k-steps.
__global__ void k_precomp(const float* __restrict__ X, int n_rows,
                          const float* __restrict__ W, const float* __restrict__ b,
                          const float* __restrict__ v1, const float* __restrict__ v2,
                          int mode) {
    extern __shared__ float sm[];
    float* Wt  = sm;                    // 128*132
    float* xs  = Wt + DIM * 132;        // 64*128
    float* sv1 = xs + 64 * DIM;         // 128
    float* sv2 = sv1 + DIM;             // 128

    float* out_m  = (mode == 0) ? g_m_node : g_m_rel;
    float* out_s1 = (mode == 0) ? g_s_src  : g_s_rel;
    float* out_s2 = (mode == 0) ? g_s_tgt  : g_dummy;

    int tid = threadIdx.x;
    for (int idx = tid; idx < DIM * DIM; idx += blockDim.x) {
        int j = idx >> 7, k = idx & 127;
        Wt[k * 132 + j] = W[idx];
    }
    for (int k = tid; k < DIM; k += blockDim.x) { sv1[k] = v1[k]; sv2[k] = v2[k]; }

    int base = blockIdx.x * 64;
    for (int idx = tid; idx < 64 * (DIM / 4); idx += blockDim.x) {
        int n = idx >> 5, c = idx & 31;
        int row = base + n;
        float4 v = make_float4(0.f, 0.f, 0.f, 0.f);
        if (row < n_rows) v = ((const float4*)X)[row * (DIM / 4) + c];
        ((float4*)xs)[n * (DIM / 4) + c] = v;
    }
    __syncthreads();

    int warp = tid >> 5, lane = tid & 31;
    F4U bu; bu.f4 = ((const float4*)b)[lane];

    unsigned long long alo[8], ahi[8];
#pragma unroll
    for (int i = 0; i < 8; i++) { alo[i] = bu.u[0]; ahi[i] = bu.u[1]; }

    int n0 = warp * 8;
    const float4* xr4 = (const float4*)(xs + n0 * DIM);   // row stride 32 float4
    const float4* Wt4 = (const float4*)Wt;                // row stride 33 float4

#pragma unroll 2
    for (int k4 = 0; k4 < DIM / 4; k4++) {
        float4 xv[8];
#pragma unroll
        for (int i = 0; i < 8; i++) xv[i] = xr4[i * 32 + k4];
#pragma unroll
        for (int q = 0; q < 4; q++) {
            int k = k4 * 4 + q;
            F4U w; w.f4 = Wt4[k * 33 + lane];
#pragma unroll
            for (int i = 0; i < 8; i++) {
                float xc = (q == 0) ? xv[i].x : (q == 1) ? xv[i].y
                         : (q == 2) ? xv[i].z : xv[i].w;
                unsigned long long xx = pack2(xc);
                alo[i] = fma2(w.u[0], xx, alo[i]);
                ahi[i] = fma2(w.u[1], xx, ahi[i]);
            }
        }
    }

    const float* xr0 = xs + n0 * DIM;
#pragma unroll
    for (int i = 0; i < 8; i++) {
        int row = base + n0 + i;
        if (row >= n_rows) break;
        F4U o; o.u[0] = alo[i]; o.u[1] = ahi[i];
        ((float4*)out_m)[row * (DIM / 4) + lane] = o.f4;
        const float* xr = xr0 + i * DIM;
        float p1 = 0.f, p2 = 0.f;
#pragma unroll
        for (int q = 0; q < 4; q++) {
            int k = lane * 4 + q;
            float xv = xr[k];
            p1 += xv * sv1[k];
            p2 += xv * sv2[k];
        }
#pragma unroll
        for (int o2 = 16; o2; o2 >>= 1) {
            p1 += __shfl_down_sync(0xffffffffu, p1, o2);
            p2 += __shfl_down_sync(0xffffffffu, p2, o2);
        }
        if (lane == 0) { out_s1[row] = p1; out_s2[row] = p2; }
    }
}

// ---------------------------------------------------------------------------
__global__ void k_hist(const int4* __restrict__ dst4) {
    int i = blockIdx.x * blockDim.x + threadIdx.x;
    if (i >= N_EDGES / 4) return;
    int4 d = dst4[i];
    atomicAdd(&g_count[d.x], 1);
    atomicAdd(&g_count[d.y], 1);
    atomicAdd(&g_count[d.z], 1);
    atomicAdd(&g_count[d.w], 1);
}

__global__ void k_scan_local() {
    __shared__ int s[1024];
    int tid = threadIdx.x;
    int idx = blockIdx.x * 1024 + tid;
    int v = (idx < N_NODES) ? g_count[idx] : 0;
    s[tid] = v;
    __syncthreads();
#pragma unroll
    for (int off = 1; off < 1024; off <<= 1) {
        int t = (tid >= off) ? s[tid - off] : 0;
        __syncthreads();
        s[tid] += t;
        __syncthreads();
    }
    if (idx < N_NODES) g_offset[idx] = s[tid] - v;   // exclusive within chunk
    if (tid == 1023) g_blocksum[blockIdx.x] = s[tid];
}

__global__ void k_scan_carry() {
    if (threadIdx.x == 0 && blockIdx.x == 0) {
        int run = 0;
        for (int c = 0; c < SCAN_CHUNKS; c++) {
            g_carry[c] = run;
            run += g_blocksum[c];
        }
        g_offset[N_NODES] = N_EDGES;
    }
}

__global__ void k_scan_add() {
    int idx = blockIdx.x * blockDim.x + threadIdx.x;
    if (idx < N_NODES) {
        int v = g_offset[idx] + g_carry[idx >> 10];
        g_offset[idx] = v;
        g_cursor[idx] = v;
        g_count[idx]  = 0;   // restore invariant for next execution
    }
}

__global__ void k_fill(const int4* __restrict__ src4, const int4* __restrict__ dst4,
                       const int4* __restrict__ rel4) {
    int i = blockIdx.x * blockDim.x + threadIdx.x;
    if (i >= N_EDGES / 4) return;
    int4 s = src4[i];
    int4 d = dst4[i];
    int4 r = rel4[i];
    int p0 = atomicAdd(&g_cursor[d.x], 1);
    int p1 = atomicAdd(&g_cursor[d.y], 1);
    int p2 = atomicAdd(&g_cursor[d.z], 1);
    int p3 = atomicAdd(&g_cursor[d.w], 1);
    g_epack[p0] = (unsigned)s.x | ((unsigned)r.x << 16);
    g_epack[p1] = (unsigned)s.y | ((unsigned)r.y << 16);
    g_epack[p2] = (unsigned)s.z | ((unsigned)r.z << 16);
    g_epack[p3] = (unsigned)s.w | ((unsigned)r.w << 16);
}

// ---------------------------------------------------------------------------
// One warp per dst node: lane-parallel score phase, shuffled gather phase.
__global__ void k_node_agg(const float* __restrict__ node_emb,
                           const float* __restrict__ attn_b,
                           float* __restrict__ out) {
    int gid = blockIdx.x * blockDim.x + threadIdx.x;
    int n = gid >> 5;
    if (n >= N_NODES) return;
    int lane = gid & 31;
    int beg = g_offset[n], end = g_offset[n + 1];
    int cnt = end - beg;

    if (cnt == 0) {
        ((float4*)out)[n * (DIM / 4) + lane] = ((const float4*)node_emb)[n * (DIM / 4) + lane];
        return;
    }

    const float4* mn4 = (const float4*)g_m_node;
    const float4* mr4 = (const float4*)g_m_rel;
    float st = g_s_tgt[n] + attn_b[0];
    float4 acc = make_float4(0.f, 0.f, 0.f, 0.f);
    float denom = 0.f;

    for (int base = 0; base < cnt; base += 32) {
        int m = cnt - base; if (m > 32) m = 32;
        unsigned pe = 0; float exl = 0.f;
        if (lane < m) {
            pe = g_epack[beg + base + lane];
            exl = __expf(g_s_src[pe & 0xFFFF] + g_s_rel[pe >> 16] + st);
        }
        denom += exl;
#pragma unroll 4
        for (int j = 0; j < m; j++) {
            unsigned p = __shfl_sync(0xffffffffu, pe, j);
            float ex = __shfl_sync(0xffffffffu, exl, j);
            int s = p & 0xFFFF, r = p >> 16;
            float4 mv = mn4[s * (DIM / 4) + lane];
            float4 rv = mr4[r * (DIM / 4) + lane];
            acc.x += ex * (mv.x + rv.x);
            acc.y += ex * (mv.y + rv.y);
            acc.z += ex * (mv.z + rv.z);
            acc.w += ex * (mv.w + rv.w);
        }
    }
#pragma unroll
    for (int o = 16; o; o >>= 1) denom += __shfl_xor_sync(0xffffffffu, denom, o);

    float inv = 1.f / denom;
    float4 res = make_float4(acc.x * inv, acc.y * inv, acc.z * inv, acc.w * inv);
    ((float4*)out)[n * (DIM / 4) + lane] = res;
}

// ---------------------------------------------------------------------------
extern "C" void kernel_launch(void* const* d_in, const int* in_sizes, int n_in,
                              void* d_out, int out_size) {
    const float* node_emb = (const float*)d_in[0];
    const float* rel_emb  = (const float*)d_in[1];
    const float* Wn       = (const float*)d_in[2];
    const float* bn       = (const float*)d_in[3];
    const float* Wr       = (const float*)d_in[4];
    const float* br       = (const float*)d_in[5];
    const float* attn_w   = (const float*)d_in[6];
    const float* attn_b   = (const float*)d_in[7];
    const int*   src      = (const int*)d_in[8];
    const int*   dst      = (const int*)d_in[9];
    const int*   rel      = (const int*)d_in[10];
    float* out = (float*)d_out;

    const int SMEM = (DIM * 132 + 64 * DIM + 2 * DIM) * (int)sizeof(float);  // 101,376 B
    cudaFuncSetAttribute(k_precomp, cudaFuncAttributeMaxDynamicSharedMemorySize, SMEM);

    int eb4 = (N_EDGES / 4 + 255) / 256;
    int nb  = (N_NODES + 255) / 256;

    k_precomp<<<(N_NODES + 63) / 64, 256, SMEM>>>(node_emb, N_NODES, Wn, bn,
                                                  attn_w, attn_w + DIM, 0);
    k_precomp<<<(N_RELS + 63) / 64, 256, SMEM>>>(rel_emb, N_RELS, Wr, br,
                                                 attn_w + 2 * DIM, attn_w + 2 * DIM, 1);
    k_hist<<<eb4, 256>>>((const int4*)dst);
    k_scan_local<<<SCAN_CHUNKS, 1024>>>();
    k_scan_carry<<<1, 32>>>();
    k_scan_add<<<nb, 256>>>();
    k_fill<<<eb4, 256>>>((const int4*)src, (const int4*)dst, (const int4*)rel);
    k_node_agg<<<(N_NODES * 32 + 255) / 256, 256>>>(node_emb, attn_b, out);
}

// round 5
// speedup vs baseline: 1.0733x; 1.0733x over previous
#include <cuda_runtime.h>
#include <math.h>

#define N_NODES 50000
#define N_EDGES 600000
#define N_RELS  500
#define DIM     128
#define SCAN_CHUNKS ((N_NODES + 1023) / 1024)   // 49

// ---- scratch (no allocations allowed) ----
__device__ __align__(16) float g_m_node[N_NODES * DIM];
__device__ __align__(16) float g_m_rel[N_RELS * DIM];
__device__ float g_s_src[N_NODES];
__device__ float g_s_tgt[N_NODES];
__device__ float g_s_rel[N_RELS];
__device__ float g_dummy[N_RELS];
__device__ int   g_count[N_NODES];       // zero-init; re-zeroed by k_scan_add each run
__device__ int   g_offset[N_NODES + 1];
__device__ int   g_cursor[N_NODES];
__device__ int   g_blocksum[SCAN_CHUNKS];
__device__ unsigned g_epack[N_EDGES];    // src | rel<<16  (src<65536, rel<500)

// ---------------------------------------------------------------------------
__device__ __forceinline__ unsigned long long fma2(unsigned long long a,
                                                   unsigned long long b,
                                                   unsigned long long c) {
    unsigned long long d;
    asm("fma.rn.f32x2 %0, %1, %2, %3;" : "=l"(d) : "l"(a), "l"(b), "l"(c));
    return d;
}
__device__ __forceinline__ unsigned long long pack2(float x) {
    unsigned long long d;
    asm("mov.b64 %0, {%1, %1};" : "=l"(d) : "r"(__float_as_uint(x)));
    return d;
}
union F4U { float4 f4; unsigned long long u[2]; };

// ---------------------------------------------------------------------------
// Row transform: m = x @ W^T + b ; s1 = x.v1 ; s2 = x.v2
// One block = 64 rows (8 warps x 8 rows). W^T staged in smem, f32x2 FFMA.
// Node pass additionally performs the dst histogram (independent atomics,
// hidden under the GEMM).
__global__ void k_precomp(const float* __restrict__ X, int n_rows,
                          const float* __restrict__ W, const float* __restrict__ b,
                          const float* __restrict__ v1, const float* __restrict__ v2,
                          const int4* __restrict__ dst4, int n_hist4,
                          int mode) {
    extern __shared__ float sm[];
    float* Wt  = sm;                    // 128*132
    float* xs  = Wt + DIM * 132;        // 64*128
    float* sv1 = xs + 64 * DIM;         // 128
    float* sv2 = sv1 + DIM;             // 128

    float* out_m  = (mode == 0) ? g_m_node : g_m_rel;
    float* out_s1 = (mode == 0) ? g_s_src  : g_s_rel;
    float* out_s2 = (mode == 0) ? g_s_tgt  : g_dummy;

    int tid = threadIdx.x;

    // fused histogram (fire-and-forget atomics; complete by kernel end)
    for (int i = blockIdx.x * blockDim.x + tid; i < n_hist4; i += gridDim.x * blockDim.x) {
        int4 d = dst4[i];
        atomicAdd(&g_count[d.x], 1);
        atomicAdd(&g_count[d.y], 1);
        atomicAdd(&g_count[d.z], 1);
        atomicAdd(&g_count[d.w], 1);
    }

    for (int idx = tid; idx < DIM * DIM; idx += blockDim.x) {
        int j = idx >> 7, k = idx & 127;
        Wt[k * 132 + j] = W[idx];
    }
    for (int k = tid; k < DIM; k += blockDim.x) { sv1[k] = v1[k]; sv2[k] = v2[k]; }

    int base = blockIdx.x * 64;
    for (int idx = tid; idx < 64 * (DIM / 4); idx += blockDim.x) {
        int n = idx >> 5, c = idx & 31;
        int row = base + n;
        float4 v = make_float4(0.f, 0.f, 0.f, 0.f);
        if (row < n_rows) v = ((const float4*)X)[row * (DIM / 4) + c];
        ((float4*)xs)[n * (DIM / 4) + c] = v;
    }
    __syncthreads();

    int warp = tid >> 5, lane = tid & 31;
    F4U bu; bu.f4 = ((const float4*)b)[lane];

    unsigned long long alo[8], ahi[8];
#pragma unroll
    for (int i = 0; i < 8; i++) { alo[i] = bu.u[0]; ahi[i] = bu.u[1]; }

    int n0 = warp * 8;
    const float4* xr4 = (const float4*)(xs + n0 * DIM);   // row stride 32 float4
    const float4* Wt4 = (const float4*)Wt;                // row stride 33 float4

#pragma unroll 2
    for (int k4 = 0; k4 < DIM / 4; k4++) {
        float4 xv[8];
#pragma unroll
        for (int i = 0; i < 8; i++) xv[i] = xr4[i * 32 + k4];
#pragma unroll
        for (int q = 0; q < 4; q++) {
            int k = k4 * 4 + q;
            F4U w; w.f4 = Wt4[k * 33 + lane];
#pragma unroll
            for (int i = 0; i < 8; i++) {
                float xc = (q == 0) ? xv[i].x : (q == 1) ? xv[i].y
                         : (q == 2) ? xv[i].z : xv[i].w;
                unsigned long long xx = pack2(xc);
                alo[i] = fma2(w.u[0], xx, alo[i]);
                ahi[i] = fma2(w.u[1], xx, ahi[i]);
            }
        }
    }

    const float* xr0 = xs + n0 * DIM;
#pragma unroll
    for (int i = 0; i < 8; i++) {
        int row = base + n0 + i;
        if (row >= n_rows) break;
        F4U o; o.u[0] = alo[i]; o.u[1] = ahi[i];
        ((float4*)out_m)[row * (DIM / 4) + lane] = o.f4;
        const float* xr = xr0 + i * DIM;
        float p1 = 0.f, p2 = 0.f;
#pragma unroll
        for (int q = 0; q < 4; q++) {
            int k = lane * 4 + q;
            float xv = xr[k];
            p1 += xv * sv1[k];
            p2 += xv * sv2[k];
        }
#pragma unroll
        for (int o2 = 16; o2; o2 >>= 1) {
            p1 += __shfl_down_sync(0xffffffffu, p1, o2);
            p2 += __shfl_down_sync(0xffffffffu, p2, o2);
        }
        if (lane == 0) { out_s1[row] = p1; out_s2[row] = p2; }
    }
}

// ---------------------------------------------------------------------------
__global__ void k_scan_local() {
    __shared__ int s[1024];
    int tid = threadIdx.x;
    int idx = blockIdx.x * 1024 + tid;
    int v = (idx < N_NODES) ? g_count[idx] : 0;
    s[tid] = v;
    __syncthreads();
#pragma unroll
    for (int off = 1; off < 1024; off <<= 1) {
        int t = (tid >= off) ? s[tid - off] : 0;
        __syncthreads();
        s[tid] += t;
        __syncthreads();
    }
    if (idx < N_NODES) g_offset[idx] = s[tid] - v;   // exclusive within chunk
    if (tid == 1023) g_blocksum[blockIdx.x] = s[tid];
}

// Adds cross-chunk carry (computed per-block from the 49 blocksums),
// initializes cursors, re-zeros g_count, sets the sentinel.
__global__ void k_scan_add() {
    __shared__ int s_carry;
    int tid = threadIdx.x;
    int blk = blockIdx.x;
    int chunk = (blk * 256) >> 10;      // 256 nodes per block, all in one chunk

    if (tid < 32) {
        int v = 0;
        if (tid < chunk) v += g_blocksum[tid];
        if (tid + 32 < chunk) v += g_blocksum[tid + 32];
#pragma unroll
        for (int o = 16; o; o >>= 1) v += __shfl_xor_sync(0xffffffffu, v, o);
        if (tid == 0) s_carry = v;
    }
    __syncthreads();
    int carry = s_carry;

    int idx = blk * 256 + tid;
    if (idx < N_NODES) {
        int v = g_offset[idx] + carry;
        g_offset[idx] = v;
        g_cursor[idx] = v;
        g_count[idx]  = 0;   // restore invariant for next execution
    }
    if (idx == 0) g_offset[N_NODES] = N_EDGES;
}

__global__ void k_fill(const int4* __restrict__ src4, const int4* __restrict__ dst4,
                       const int4* __restrict__ rel4) {
    int i = blockIdx.x * blockDim.x + threadIdx.x;
    if (i >= N_EDGES / 4) return;
    int4 s = src4[i];
    int4 d = dst4[i];
    int4 r = rel4[i];
    int p0 = atomicAdd(&g_cursor[d.x], 1);
    int p1 = atomicAdd(&g_cursor[d.y], 1);
    int p2 = atomicAdd(&g_cursor[d.z], 1);
    int p3 = atomicAdd(&g_cursor[d.w], 1);
    g_epack[p0] = (unsigned)s.x | ((unsigned)r.x << 16);
    g_epack[p1] = (unsigned)s.y | ((unsigned)r.y << 16);
    g_epack[p2] = (unsigned)s.z | ((unsigned)r.z << 16);
    g_epack[p3] = (unsigned)s.w | ((unsigned)r.w << 16);
}

// ---------------------------------------------------------------------------
// One warp per dst node: fused softmax + weighted aggregate + fallback.
// (R3-proven form: warp-broadcast scalar loads, serial edge loop.)
__global__ void k_node_agg(const float* __restrict__ node_emb,
                           const float* __restrict__ attn_b,
                           float* __restrict__ out) {
    int gid = blockIdx.x * blockDim.x + threadIdx.x;
    int n = gid >> 5;
    if (n >= N_NODES) return;
    int lane = gid & 31;
    int beg = g_offset[n], end = g_offset[n + 1];
    float4 res;
    if (end > beg) {
        float st = g_s_tgt[n] + attn_b[0];
        float4 acc = make_float4(0.f, 0.f, 0.f, 0.f);
        float denom = 0.f;
        for (int e = beg; e < end; e++) {
            unsigned p = g_epack[e];
            int s = p & 0xFFFF;
            int r = p >> 16;
            float ex = __expf(g_s_src[s] + g_s_rel[r] + st);
            float4 mv = ((const float4*)g_m_node)[s * (DIM / 4) + lane];
            float4 rv = ((const float4*)g_m_rel)[r * (DIM / 4) + lane];
            acc.x += ex * (mv.x + rv.x);
            acc.y += ex * (mv.y + rv.y);
            acc.z += ex * (mv.z + rv.z);
            acc.w += ex * (mv.w + rv.w);
            denom += ex;
        }
        float inv = 1.f / denom;
        res = make_float4(acc.x * inv, acc.y * inv, acc.z * inv, acc.w * inv);
    } else {
        res = ((const float4*)node_emb)[n * (DIM / 4) + lane];
    }
    ((float4*)out)[n * (DIM / 4) + lane] = res;
}

// ---------------------------------------------------------------------------
extern "C" void kernel_launch(void* const* d_in, const int* in_sizes, int n_in,
                              void* d_out, int out_size) {
    const float* node_emb = (const float*)d_in[0];
    const float* rel_emb  = (const float*)d_in[1];
    const float* Wn       = (const float*)d_in[2];
    const float* bn       = (const float*)d_in[3];
    const float* Wr       = (const float*)d_in[4];
    const float* br       = (const float*)d_in[5];
    const float* attn_w   = (const float*)d_in[6];
    const float* attn_b   = (const float*)d_in[7];
    const int*   src      = (const int*)d_in[8];
    const int*   dst      = (const int*)d_in[9];
    const int*   rel      = (const int*)d_in[10];
    float* out = (float*)d_out;

    const int SMEM = (DIM * 132 + 64 * DIM + 2 * DIM) * (int)sizeof(float);  // 101,376 B
    cudaFuncSetAttribute(k_precomp, cudaFuncAttributeMaxDynamicSharedMemorySize, SMEM);

    int eb4 = (N_EDGES / 4 + 255) / 256;

    k_precomp<<<(N_NODES + 63) / 64, 256, SMEM>>>(node_emb, N_NODES, Wn, bn,
                                                  attn_w, attn_w + DIM,
                                                  (const int4*)dst, N_EDGES / 4, 0);
    k_precomp<<<(N_RELS + 63) / 64, 256, SMEM>>>(rel_emb, N_RELS, Wr, br,
                                                 attn_w + 2 * DIM, attn_w + 2 * DIM,
                                                 (const int4*)dst, 0, 1);
    k_scan_local<<<SCAN_CHUNKS, 1024>>>();
    k_scan_add<<<(N_NODES + 255) / 256, 256>>>();
    k_fill<<<eb4, 256>>>((const int4*)src, (const int4*)dst, (const int4*)rel);
    k_node_agg<<<(N_NODES * 32 + 255) / 256, 256>>>(node_emb, attn_b, out);
}